// round 10
// baseline (speedup 1.0000x reference)
#include <cuda_runtime.h>
#include <math.h>
#include <stdint.h>

#define NN 50000
#define NE 800000
#define MUL 32
#define AA 8
#define VE 4
#define FCI 16
#define FCH 64
#define W_NUMEL 128

// ---------- scratch (device-code-only symbols; never passed from host) ----------
__device__ __align__(16) float g_x[NN * MUL];     // lin1 output
__device__ __align__(16) float g_sc[NN * MUL];    // self-connection output
__device__ __align__(16) float g_agg[NN * MUL];   // scatter-add accumulator
__device__ __align__(16) float g_nf[NN * MUL];    // node features between layers
__device__ __align__(16) float g_ea[NE * VE];     // edge attrs between layers

// ---------------------------------------------------------------
__global__ void zero_agg_kernel() {
    int i = blockIdx.x * blockDim.x + threadIdx.x;
    if (i < NN * MUL) g_agg[i] = 0.0f;
}

// Dual fctp: blocks [0, ng) compute sc_w -> g_sc ; blocks [ng, 2ng) compute lin1_w -> g_x
__global__ __launch_bounds__(256) void fctp_dual_kernel(
    const float* __restrict__ a, const float* __restrict__ b,
    const float* __restrict__ w_sc, const float* __restrict__ w_lin1, int ng)
{
    __shared__ float ws[MUL * AA * MUL];  // 32KB
    int half = (blockIdx.x >= ng) ? 1 : 0;
    const float* w = half ? w_lin1 : w_sc;
    for (int i = threadIdx.x; i < MUL * AA * MUL; i += 256) ws[i] = w[i];
    __syncthreads();

    int blk = half ? (blockIdx.x - ng) : blockIdx.x;
    int n = blk * 256 + threadIdx.x;
    if (n >= NN) return;
    const float* ap = a ? a : g_nf;
    float* out = half ? g_x : g_sc;

    float attr[AA];
#pragma unroll
    for (int v = 0; v < AA; v++) attr[v] = b[n * AA + v];

    float4 acc4[8];
#pragma unroll
    for (int k4 = 0; k4 < 8; k4++) acc4[k4] = make_float4(0.f, 0.f, 0.f, 0.f);

    const float4* arow = (const float4*)(ap + (size_t)n * MUL);
    for (int u4 = 0; u4 < 8; u4++) {
        float4 av = arow[u4];
        float au[4] = {av.x, av.y, av.z, av.w};
#pragma unroll
        for (int uu = 0; uu < 4; uu++) {
            int u = u4 * 4 + uu;
#pragma unroll
            for (int v = 0; v < AA; v++) {
                float p = au[uu] * attr[v];
                const float4* wp = (const float4*)&ws[(u * AA + v) * MUL];
#pragma unroll
                for (int k4 = 0; k4 < 8; k4++) {
                    float4 wv = wp[k4];
                    acc4[k4].x += p * wv.x;
                    acc4[k4].y += p * wv.y;
                    acc4[k4].z += p * wv.z;
                    acc4[k4].w += p * wv.w;
                }
            }
        }
    }
    const float s = 1.0f / 16.0f;
    float4* op = (float4*)(out + (size_t)n * MUL);
#pragma unroll
    for (int k4 = 0; k4 < 8; k4++) {
        float4 o = acc4[k4];
        o.x *= s; o.y *= s; o.z *= s; o.w *= s;
        op[k4] = o;
    }
}

// lin2 + alpha + combine (+ optional sin). out == nullptr -> write g_nf
__global__ __launch_bounds__(256) void node_post_kernel(
    const float* __restrict__ b, const float* __restrict__ lin2w,
    const float* __restrict__ alw, float* __restrict__ out, int apply_sin)
{
    __shared__ float ws[MUL * AA * MUL];  // 32KB
    __shared__ float as[MUL * AA];        // 1KB
    for (int i = threadIdx.x; i < MUL * AA * MUL; i += 256) ws[i] = lin2w[i];
    for (int i = threadIdx.x; i < MUL * AA; i += 256) as[i] = alw[i];
    __syncthreads();

    int n = blockIdx.x * 256 + threadIdx.x;
    if (n >= NN) return;
    float* op = out ? out : g_nf;

    float attr[AA];
#pragma unroll
    for (int v = 0; v < AA; v++) attr[v] = b[n * AA + v];

    float4 acc4[8];
#pragma unroll
    for (int k4 = 0; k4 < 8; k4++) acc4[k4] = make_float4(0.f, 0.f, 0.f, 0.f);
    float aacc = 0.0f;

    const float4* arow = (const float4*)(g_agg + (size_t)n * MUL);
    for (int u4 = 0; u4 < 8; u4++) {
        float4 av = arow[u4];
        float au[4] = {av.x, av.y, av.z, av.w};
#pragma unroll
        for (int uu = 0; uu < 4; uu++) {
            int u = u4 * 4 + uu;
#pragma unroll
            for (int v = 0; v < AA; v++) {
                float p = au[uu] * attr[v];
                aacc += p * as[u * AA + v];
                const float4* wp = (const float4*)&ws[(u * AA + v) * MUL];
#pragma unroll
                for (int k4 = 0; k4 < 8; k4++) {
                    float4 wv = wp[k4];
                    acc4[k4].x += p * wv.x;
                    acc4[k4].y += p * wv.y;
                    acc4[k4].z += p * wv.z;
                    acc4[k4].w += p * wv.w;
                }
            }
        }
    }
    const float s = 1.0f / 16.0f;
    float alpha = aacc * s;
    const float4* scp = (const float4*)(g_sc + (size_t)n * MUL);
    float4* outp = (float4*)(op + (size_t)n * MUL);
#pragma unroll
    for (int k4 = 0; k4 < 8; k4++) {
        float4 sc = scp[k4];
        float4 cv = acc4[k4];
        float4 o;
        o.x = sc.x + alpha * (cv.x * s);
        o.y = sc.y + alpha * (cv.y * s);
        o.z = sc.z + alpha * (cv.z * s);
        o.w = sc.w + alpha * (cv.w * s);
        if (apply_sin) { o.x = sinf(o.x); o.y = sinf(o.y); o.z = sinf(o.z); o.w = sinf(o.w); }
        outp[k4] = o;
    }
}

// ---------------- MMA helpers ----------------
__device__ __forceinline__ uint32_t f2tf32(float f) {
    uint32_t r;
    asm("cvt.rna.tf32.f32 %0, %1;" : "=r"(r) : "f"(f));
    return r;
}
// split f into tf32 hi + tf32 lo (3xTF32 scheme)
__device__ __forceinline__ void tf32_split(float f, uint32_t& hi, uint32_t& lo) {
    hi = f2tf32(f);
    float res = f - __uint_as_float(hi);
    lo = f2tf32(res);
}
__device__ __forceinline__ void mma_tf32(float* c, const uint32_t* a, const uint32_t* b) {
    asm volatile(
        "mma.sync.aligned.m16n8k8.row.col.f32.tf32.tf32.f32 "
        "{%0,%1,%2,%3},{%4,%5,%6,%7},{%8,%9},{%0,%1,%2,%3};"
        : "+f"(c[0]), "+f"(c[1]), "+f"(c[2]), "+f"(c[3])
        : "r"(a[0]), "r"(a[1]), "r"(a[2]), "r"(a[3]), "r"(b[0]), "r"(b[1]));
}

// 16B-aligned 4-wide global float add (native vector atomic on sm_90+).
__device__ __forceinline__ void red_add_v4(float* ptr, float a, float b, float c, float d)
{
#if defined(__CUDA_ARCH__) && (__CUDA_ARCH__ >= 900) && (CUDART_VERSION >= 12080)
    atomicAdd((float4*)ptr, make_float4(a, b, c, d));
#else
    atomicAdd(ptr + 0, a);
    atomicAdd(ptr + 1, b);
    atomicAdd(ptr + 2, c);
    atomicAdd(ptr + 3, d);
#endif
}

// smem layout (floats) for edge_mma_kernel
#define HS_STRIDE 68
#define XS_STRIDE 36
#define OFF_HS   0
#define OFF_WS   (128 * HS_STRIDE)                 // 8704
#define OFF_XS   (OFF_WS + 128 * HS_STRIDE)        // 17408
#define OFF_W0   (OFF_XS + 128 * XS_STRIDE)        // 22016
#define OFF_SCE  (OFF_W0 + FCI * FCH)              // 23040
#define OFF_EAS  (OFF_SCE + MUL * VE * VE)         // 23552
#define OFF_DSS  (OFF_EAS + 128 * 4)               // 24064
#define SMEM_FLOATS (OFF_DSS + 128)                // 24192
#define SMEM_BYTES (SMEM_FLOATS * 4)               // 96768

// Fused edge kernel: FC0+sin (per-thread) -> smem H -> 3xTF32 MMA GEMM (H @ W1t)
// -> warp-local TP epilogue -> v4 RED scatter + edge update. 128 edges/block.
__global__ __launch_bounds__(128) void edge_mma_kernel(
    const float* __restrict__ es, const int* __restrict__ src,
    const int* __restrict__ dst, const float* __restrict__ ea_in_p,
    float* __restrict__ ea_out_p, const float* __restrict__ fw0,
    const float* __restrict__ fw1, const float* __restrict__ scew)
{
    extern __shared__ float sm[];
    float* Hs   = sm + OFF_HS;    // [128][68] row = edge, col = j (fp32 h)
    float* Ws   = sm + OFF_WS;    // [128][68] row = n (=4u+v), col = j (fp32 W1t)
    float* xs   = sm + OFF_XS;    // [128][36] x[src[e]]
    float* w0s  = sm + OFF_W0;    // FC0 weights
    float* sces = sm + OFF_SCE;   // sce weights
    float* eas  = sm + OFF_EAS;   // [128][4] edge attrs
    int*   dss  = (int*)(sm + OFF_DSS);  // [128] dst

    int tid = threadIdx.x;
    for (int i = tid; i < FCI * FCH; i += 128) w0s[i] = fw0[i];
    for (int i = tid; i < FCH * W_NUMEL; i += 128) {
        int n = i >> 6, j = i & 63;
        Ws[n * HS_STRIDE + j] = fw1[j * W_NUMEL + n];
    }
    for (int i = tid; i < MUL * VE * VE; i += 128) sces[i] = scew[i];
    __syncthreads();

    const float* ea_in = ea_in_p ? ea_in_p : g_ea;
    float* ea_out = ea_out_p ? ea_out_p : g_ea;

    int ge = blockIdx.x * 128 + tid;   // NE = 128*6250, always in range

    // ---- h phase: FC0 + sin for this thread's edge ----
    {
        float scl[FCI];
        const float4* esp = (const float4*)(es + (size_t)ge * FCI);
#pragma unroll
        for (int i = 0; i < 4; i++) {
            float4 tv = esp[i];
            scl[4 * i + 0] = tv.x; scl[4 * i + 1] = tv.y;
            scl[4 * i + 2] = tv.z; scl[4 * i + 3] = tv.w;
        }
        float h[FCH];
#pragma unroll
        for (int j = 0; j < FCH; j++) h[j] = 0.0f;
#pragma unroll
        for (int i = 0; i < FCI; i++) {
            float si = scl[i];
            const float4* wr = (const float4*)&w0s[i * FCH];
#pragma unroll
            for (int j4 = 0; j4 < FCH / 4; j4++) {
                float4 wv = wr[j4];
                h[4 * j4 + 0] += si * wv.x;
                h[4 * j4 + 1] += si * wv.y;
                h[4 * j4 + 2] += si * wv.z;
                h[4 * j4 + 3] += si * wv.w;
            }
        }
        float4* hrow = (float4*)(Hs + tid * HS_STRIDE);
#pragma unroll
        for (int q = 0; q < 16; q++) {
            hrow[q] = make_float4(__sinf(h[4 * q + 0] * 0.25f), __sinf(h[4 * q + 1] * 0.25f),
                                  __sinf(h[4 * q + 2] * 0.25f), __sinf(h[4 * q + 3] * 0.25f));
        }
    }
    int sv = src[ge];
    dss[tid] = dst[ge];
    *(float4*)(eas + tid * 4) = *(const float4*)(ea_in + (size_t)ge * VE);
    {
        const float4* xr = (const float4*)(g_x + (size_t)sv * MUL);
        float4* xd = (float4*)(xs + tid * XS_STRIDE);
#pragma unroll
        for (int q = 0; q < 8; q++) xd[q] = xr[q];
    }
    __syncwarp();   // each warp only consumes rows written by its own threads

    // ---- MMA + epilogue: warp wp owns edges [32*wp, 32*wp+32) ----
    int lane = tid & 31, wp = tid >> 5, g = lane >> 2, t = lane & 3;

    float ear[2][2][4];
    int dlo[2], dhi[2];
#pragma unroll
    for (int mt = 0; mt < 2; mt++) {
        int rl = wp * 32 + mt * 16 + g, rh = rl + 8;
#pragma unroll
        for (int v = 0; v < 4; v++) {
            ear[mt][0][v] = eas[rl * 4 + v];
            ear[mt][1][v] = eas[rh * 4 + v];
        }
        dlo[mt] = dss[rl]; dhi[mt] = dss[rh];
    }

    float racc[2][2][4];
#pragma unroll
    for (int mt = 0; mt < 2; mt++)
#pragma unroll
        for (int i = 0; i < 2; i++)
#pragma unroll
            for (int v = 0; v < 4; v++) racc[mt][i][v] = 0.f;

    int vb = (2 * t) & 3;   // 0 or 2: v-base of this lane's acc pair

#pragma unroll 1
    for (int ng = 0; ng < 4; ng++) {
        float acc[2][4][4];
#pragma unroll
        for (int mt = 0; mt < 2; mt++)
#pragma unroll
            for (int nt = 0; nt < 4; nt++)
#pragma unroll
                for (int i = 0; i < 4; i++) acc[mt][nt][i] = 0.f;

#pragma unroll 1
        for (int k0 = 0; k0 < 64; k0 += 8) {
            uint32_t ahi[2][4], alo[2][4];
#pragma unroll
            for (int mt = 0; mt < 2; mt++) {
                int rb = (wp * 32 + mt * 16 + g) * HS_STRIDE + k0 + t;
                float f0 = Hs[rb];
                float f1 = Hs[rb + 8 * HS_STRIDE];
                float f2 = Hs[rb + 4];
                float f3 = Hs[rb + 8 * HS_STRIDE + 4];
                tf32_split(f0, ahi[mt][0], alo[mt][0]);
                tf32_split(f1, ahi[mt][1], alo[mt][1]);
                tf32_split(f2, ahi[mt][2], alo[mt][2]);
                tf32_split(f3, ahi[mt][3], alo[mt][3]);
            }
            uint32_t bhi[4][2], blo[4][2];
#pragma unroll
            for (int nt = 0; nt < 4; nt++) {
                int nb = (32 * ng + 8 * nt + g) * HS_STRIDE + k0 + t;
                float p0 = Ws[nb];
                float p1 = Ws[nb + 4];
                tf32_split(p0, bhi[nt][0], blo[nt][0]);
                tf32_split(p1, bhi[nt][1], blo[nt][1]);
            }
#pragma unroll
            for (int mt = 0; mt < 2; mt++)
#pragma unroll
                for (int nt = 0; nt < 4; nt++) {
                    mma_tf32(acc[mt][nt], ahi[mt], bhi[nt]);
                    mma_tf32(acc[mt][nt], ahi[mt], blo[nt]);
                    mma_tf32(acc[mt][nt], alo[mt], bhi[nt]);
                }
        }

        // ---- epilogue for this n-group (u in [8*ng, 8*ng+8)) ----
#pragma unroll
        for (int mt = 0; mt < 2; mt++) {
            int rl = wp * 32 + mt * 16 + g, rh = rl + 8;
            float efl[4], efh[4];
#pragma unroll
            for (int nt = 0; nt < 4; nt++) {
                float* c = acc[mt][nt];
                float pl = ear[mt][0][vb] * c[0] + ear[mt][0][vb + 1] * c[1];
                float ph = ear[mt][1][vb] * c[2] + ear[mt][1][vb + 1] * c[3];
                pl += __shfl_xor_sync(0xffffffffu, pl, 1);
                ph += __shfl_xor_sync(0xffffffffu, ph, 1);
                int u = 8 * ng + 2 * nt + (t >> 1);
                float el = xs[rl * XS_STRIDE + u] * pl * 0.0625f;
                float eh = xs[rh * XS_STRIDE + u] * ph * 0.0625f;
                efl[nt] = el; efh[nt] = eh;
                // r accumulation (t-pairs duplicate; corrected by 0.5 at the end)
                const float4* sp = (const float4*)&sces[u * 16];
                float4 s0 = sp[0], s1 = sp[1], s2 = sp[2], s3 = sp[3];
                racc[mt][0][0] += el * (ear[mt][0][0] * s0.x + ear[mt][0][1] * s1.x + ear[mt][0][2] * s2.x + ear[mt][0][3] * s3.x);
                racc[mt][0][1] += el * (ear[mt][0][0] * s0.y + ear[mt][0][1] * s1.y + ear[mt][0][2] * s2.y + ear[mt][0][3] * s3.y);
                racc[mt][0][2] += el * (ear[mt][0][0] * s0.z + ear[mt][0][1] * s1.z + ear[mt][0][2] * s2.z + ear[mt][0][3] * s3.z);
                racc[mt][0][3] += el * (ear[mt][0][0] * s0.w + ear[mt][0][1] * s1.w + ear[mt][0][2] * s2.w + ear[mt][0][3] * s3.w);
                racc[mt][1][0] += eh * (ear[mt][1][0] * s0.x + ear[mt][1][1] * s1.x + ear[mt][1][2] * s2.x + ear[mt][1][3] * s3.x);
                racc[mt][1][1] += eh * (ear[mt][1][0] * s0.y + ear[mt][1][1] * s1.y + ear[mt][1][2] * s2.y + ear[mt][1][3] * s3.y);
                racc[mt][1][2] += eh * (ear[mt][1][0] * s0.z + ear[mt][1][1] * s1.z + ear[mt][1][2] * s2.z + ear[mt][1][3] * s3.z);
                racc[mt][1][3] += eh * (ear[mt][1][0] * s0.w + ear[mt][1][1] * s1.w + ear[mt][1][2] * s2.w + ear[mt][1][3] * s3.w);
            }
            // regroup u's for v4 RED: t0 has u{0,2,4,6}+8ng, t2 has u{1,3,5,7}+8ng
            float xl[4], xh[4];
#pragma unroll
            for (int nt = 0; nt < 4; nt++) {
                xl[nt] = __shfl_xor_sync(0xffffffffu, efl[nt], 2);
                xh[nt] = __shfl_xor_sync(0xffffffffu, efh[nt], 2);
            }
            if ((t & 1) == 0) {
                int ubase = 8 * ng + ((t == 0) ? 0 : 4);
                float a0, a1, a2, a3, b0, b1, b2, b3;
                if (t == 0) {
                    a0 = efl[0]; a1 = xl[0]; a2 = efl[1]; a3 = xl[1];
                    b0 = efh[0]; b1 = xh[0]; b2 = efh[1]; b3 = xh[1];
                } else {
                    a0 = xl[2]; a1 = efl[2]; a2 = xl[3]; a3 = efl[3];
                    b0 = xh[2]; b1 = efh[2]; b2 = xh[3]; b3 = efh[3];
                }
                const float sn = 0.25f;  // segment norm 1/sqrt(16)
                red_add_v4(&g_agg[(size_t)dlo[mt] * MUL + ubase], a0 * sn, a1 * sn, a2 * sn, a3 * sn);
                red_add_v4(&g_agg[(size_t)dhi[mt] * MUL + ubase], b0 * sn, b1 * sn, b2 * sn, b3 * sn);
            }
        }
    }

    // ---- finalize edge_out: reduce racc over the 4 lanes of the group ----
#pragma unroll
    for (int mt = 0; mt < 2; mt++)
#pragma unroll
        for (int i = 0; i < 2; i++)
#pragma unroll
            for (int v = 0; v < 4; v++) {
                float val = racc[mt][i][v];
                val += __shfl_xor_sync(0xffffffffu, val, 1);
                val += __shfl_xor_sync(0xffffffffu, val, 2);
                racc[mt][i][v] = val;
            }
    const float C2 = 0.5f * 0.022097086912079608f;  // 0.5 dup-fix * 1/(4*sqrt(128))
    if (t == 0) {
#pragma unroll
        for (int mt = 0; mt < 2; mt++) {
            int rl = wp * 32 + mt * 16 + g, rh = rl + 8;
            size_t el = (size_t)(blockIdx.x * 128 + rl);
            size_t eh = (size_t)(blockIdx.x * 128 + rh);
            float4 ol = make_float4(ear[mt][0][0] + racc[mt][0][0] * C2,
                                    ear[mt][0][1] + racc[mt][0][1] * C2,
                                    ear[mt][0][2] + racc[mt][0][2] * C2,
                                    ear[mt][0][3] + racc[mt][0][3] * C2);
            float4 oh = make_float4(ear[mt][1][0] + racc[mt][1][0] * C2,
                                    ear[mt][1][1] + racc[mt][1][1] * C2,
                                    ear[mt][1][2] + racc[mt][1][2] * C2,
                                    ear[mt][1][3] + racc[mt][1][3] * C2);
            *(float4*)(ea_out + el * VE) = ol;
            *(float4*)(ea_out + eh * VE) = oh;
        }
    }
}

// ---------------------------------------------------------------
extern "C" void kernel_launch(void* const* d_in, const int* in_sizes, int n_in,
                              void* d_out, int out_size)
{
    const float* node_features = (const float*)d_in[0];
    const float* node_attr     = (const float*)d_in[1];
    const int*   edge_src      = (const int*)d_in[2];
    const int*   edge_dst      = (const int*)d_in[3];
    const float* edge_attr     = (const float*)d_in[4];
    const float* edge_scalars  = (const float*)d_in[5];
    const float* sc_w    = (const float*)d_in[6];
    const float* lin1_w  = (const float*)d_in[7];
    const float* lin2_w  = (const float*)d_in[8];
    const float* alpha_w = (const float*)d_in[9];
    const float* sce_w   = (const float*)d_in[10];
    const float* fc_w0   = (const float*)d_in[11];
    const float* fc_w1   = (const float*)d_in[12];
    float* out = (float*)d_out;

    const int need_nf = NN * MUL;
    const int need_both = NN * MUL + NE * VE;
    float* nf_final = (out_size >= need_nf) ? out : nullptr;
    float* ea_final = (out_size >= need_both) ? (out + (size_t)NN * MUL) : nullptr;

    cudaFuncSetAttribute(edge_mma_kernel,
                         cudaFuncAttributeMaxDynamicSharedMemorySize, SMEM_BYTES);

    const int node_grid = (NN + 255) / 256;
    const int edge_grid = NE / 128;   // 6250
    const int zero_grid = (NN * MUL + 255) / 256;

    for (int l = 0; l < 2; l++) {
        const float* nf_in = (l == 0) ? node_features : nullptr;  // null -> g_nf
        const float* ea_in = (l == 0) ? edge_attr : nullptr;      // null -> g_ea
        float* ea_out = (l == 1) ? ea_final : nullptr;            // null -> g_ea
        float* nf_out = (l == 1) ? nf_final : nullptr;            // null -> g_nf

        fctp_dual_kernel<<<2 * node_grid, 256>>>(nf_in, node_attr,
                                                 sc_w + (size_t)l * MUL * AA * MUL,
                                                 lin1_w + (size_t)l * MUL * AA * MUL,
                                                 node_grid);
        zero_agg_kernel<<<zero_grid, 256>>>();
        edge_mma_kernel<<<edge_grid, 128, SMEM_BYTES>>>(
            edge_scalars, edge_src, edge_dst, ea_in, ea_out,
            fc_w0 + (size_t)l * FCI * FCH,
            fc_w1 + (size_t)l * FCH * W_NUMEL,
            sce_w + (size_t)l * MUL * VE * VE);
        node_post_kernel<<<node_grid, 256>>>(node_attr,
                                             lin2_w + (size_t)l * MUL * AA * MUL,
                                             alpha_w + (size_t)l * MUL * AA,
                                             nf_out, (l == 0) ? 1 : 0);
    }
}

// round 11
// speedup vs baseline: 1.4339x; 1.4339x over previous
#include <cuda_runtime.h>
#include <math.h>
#include <stdint.h>

#define NN 50000
#define NE 800000
#define MUL 32
#define AA 8
#define VE 4
#define FCI 16
#define FCH 64
#define W_NUMEL 128

// ---------- scratch (device-code-only symbols; never passed from host) ----------
__device__ __align__(16) float g_x[NN * MUL];     // lin1 output
__device__ __align__(16) float g_sc[NN * MUL];    // self-connection output
__device__ __align__(16) float g_agg[NN * MUL];   // scatter-add accumulator
__device__ __align__(16) float g_nf[NN * MUL];    // node features between layers
__device__ __align__(16) float g_ea[NE * VE];     // edge attrs between layers
// pre-split tf32 planes of W1^T, n-major [128][64]
__device__ __align__(16) uint32_t g_w1thi[W_NUMEL * FCH];
__device__ __align__(16) uint32_t g_w1tlo[W_NUMEL * FCH];

// ---------------------------------------------------------------
__global__ void zero_agg_kernel() {
    int i = blockIdx.x * blockDim.x + threadIdx.x;
    if (i < NN * MUL) g_agg[i] = 0.0f;
}

// ---------------- MMA helpers ----------------
__device__ __forceinline__ uint32_t f2tf32(float f) {
    uint32_t r;
    asm("cvt.rna.tf32.f32 %0, %1;" : "=r"(r) : "f"(f));
    return r;
}
__device__ __forceinline__ void tf32_split(float f, uint32_t& hi, uint32_t& lo) {
    hi = f2tf32(f);
    float res = f - __uint_as_float(hi);
    lo = f2tf32(res);
}
__device__ __forceinline__ void mma_tf32(float* c, const uint32_t* a, const uint32_t* b) {
    asm volatile(
        "mma.sync.aligned.m16n8k8.row.col.f32.tf32.tf32.f32 "
        "{%0,%1,%2,%3},{%4,%5,%6,%7},{%8,%9},{%0,%1,%2,%3};"
        : "+f"(c[0]), "+f"(c[1]), "+f"(c[2]), "+f"(c[3])
        : "r"(a[0]), "r"(a[1]), "r"(a[2]), "r"(a[3]), "r"(b[0]), "r"(b[1]));
}

// prep: split W1 (j-major [64][128]) into tf32 hi/lo planes of W1^T (n-major [128][64])
__global__ void w1_split_kernel(const float* __restrict__ fw1) {
    int i = blockIdx.x * blockDim.x + threadIdx.x;   // i = n*64 + j
    if (i >= W_NUMEL * FCH) return;
    int n = i >> 6, j = i & 63;
    float f = fw1[j * W_NUMEL + n];
    uint32_t hi, lo;
    tf32_split(f, hi, lo);
    g_w1thi[i] = hi;
    g_w1tlo[i] = lo;
}

// Dual fctp: blocks [0, ng) compute sc_w -> g_sc ; blocks [ng, 2ng) compute lin1_w -> g_x
__global__ __launch_bounds__(256) void fctp_dual_kernel(
    const float* __restrict__ a, const float* __restrict__ b,
    const float* __restrict__ w_sc, const float* __restrict__ w_lin1, int ng)
{
    __shared__ float ws[MUL * AA * MUL];  // 32KB
    int half = (blockIdx.x >= ng) ? 1 : 0;
    const float* w = half ? w_lin1 : w_sc;
    for (int i = threadIdx.x; i < MUL * AA * MUL; i += 256) ws[i] = w[i];
    __syncthreads();

    int blk = half ? (blockIdx.x - ng) : blockIdx.x;
    int n = blk * 256 + threadIdx.x;
    if (n >= NN) return;
    const float* ap = a ? a : g_nf;
    float* out = half ? g_x : g_sc;

    float attr[AA];
#pragma unroll
    for (int v = 0; v < AA; v++) attr[v] = b[n * AA + v];

    float4 acc4[8];
#pragma unroll
    for (int k4 = 0; k4 < 8; k4++) acc4[k4] = make_float4(0.f, 0.f, 0.f, 0.f);

    const float4* arow = (const float4*)(ap + (size_t)n * MUL);
    for (int u4 = 0; u4 < 8; u4++) {
        float4 av = arow[u4];
        float au[4] = {av.x, av.y, av.z, av.w};
#pragma unroll
        for (int uu = 0; uu < 4; uu++) {
            int u = u4 * 4 + uu;
#pragma unroll
            for (int v = 0; v < AA; v++) {
                float p = au[uu] * attr[v];
                const float4* wp = (const float4*)&ws[(u * AA + v) * MUL];
#pragma unroll
                for (int k4 = 0; k4 < 8; k4++) {
                    float4 wv = wp[k4];
                    acc4[k4].x += p * wv.x;
                    acc4[k4].y += p * wv.y;
                    acc4[k4].z += p * wv.z;
                    acc4[k4].w += p * wv.w;
                }
            }
        }
    }
    const float s = 1.0f / 16.0f;
    float4* op = (float4*)(out + (size_t)n * MUL);
#pragma unroll
    for (int k4 = 0; k4 < 8; k4++) {
        float4 o = acc4[k4];
        o.x *= s; o.y *= s; o.z *= s; o.w *= s;
        op[k4] = o;
    }
}

// lin2 + alpha + combine (+ optional sin). out == nullptr -> write g_nf
__global__ __launch_bounds__(256) void node_post_kernel(
    const float* __restrict__ b, const float* __restrict__ lin2w,
    const float* __restrict__ alw, float* __restrict__ out, int apply_sin)
{
    __shared__ float ws[MUL * AA * MUL];  // 32KB
    __shared__ float as[MUL * AA];        // 1KB
    for (int i = threadIdx.x; i < MUL * AA * MUL; i += 256) ws[i] = lin2w[i];
    for (int i = threadIdx.x; i < MUL * AA; i += 256) as[i] = alw[i];
    __syncthreads();

    int n = blockIdx.x * 256 + threadIdx.x;
    if (n >= NN) return;
    float* op = out ? out : g_nf;

    float attr[AA];
#pragma unroll
    for (int v = 0; v < AA; v++) attr[v] = b[n * AA + v];

    float4 acc4[8];
#pragma unroll
    for (int k4 = 0; k4 < 8; k4++) acc4[k4] = make_float4(0.f, 0.f, 0.f, 0.f);
    float aacc = 0.0f;

    const float4* arow = (const float4*)(g_agg + (size_t)n * MUL);
    for (int u4 = 0; u4 < 8; u4++) {
        float4 av = arow[u4];
        float au[4] = {av.x, av.y, av.z, av.w};
#pragma unroll
        for (int uu = 0; uu < 4; uu++) {
            int u = u4 * 4 + uu;
#pragma unroll
            for (int v = 0; v < AA; v++) {
                float p = au[uu] * attr[v];
                aacc += p * as[u * AA + v];
                const float4* wp = (const float4*)&ws[(u * AA + v) * MUL];
#pragma unroll
                for (int k4 = 0; k4 < 8; k4++) {
                    float4 wv = wp[k4];
                    acc4[k4].x += p * wv.x;
                    acc4[k4].y += p * wv.y;
                    acc4[k4].z += p * wv.z;
                    acc4[k4].w += p * wv.w;
                }
            }
        }
    }
    const float s = 1.0f / 16.0f;
    float alpha = aacc * s;
    const float4* scp = (const float4*)(g_sc + (size_t)n * MUL);
    float4* outp = (float4*)(op + (size_t)n * MUL);
#pragma unroll
    for (int k4 = 0; k4 < 8; k4++) {
        float4 sc = scp[k4];
        float4 cv = acc4[k4];
        float4 o;
        o.x = sc.x + alpha * (cv.x * s);
        o.y = sc.y + alpha * (cv.y * s);
        o.z = sc.z + alpha * (cv.z * s);
        o.w = sc.w + alpha * (cv.w * s);
        if (apply_sin) { o.x = sinf(o.x); o.y = sinf(o.y); o.z = sinf(o.z); o.w = sinf(o.w); }
        outp[k4] = o;
    }
}

// 16B-aligned 4-wide global float add (native vector atomic on sm_90+).
__device__ __forceinline__ void red_add_v4(float* ptr, float a, float b, float c, float d)
{
#if defined(__CUDA_ARCH__) && (__CUDA_ARCH__ >= 900) && (CUDART_VERSION >= 12080)
    atomicAdd((float4*)ptr, make_float4(a, b, c, d));
#else
    atomicAdd(ptr + 0, a);
    atomicAdd(ptr + 1, b);
    atomicAdd(ptr + 2, c);
    atomicAdd(ptr + 3, d);
#endif
}

// smem layout (floats) for edge_mma_kernel  (W planes now live in global/L1)
#define HS_STRIDE 68
#define XS_STRIDE 36
#define OFF_HS   0
#define OFF_XS   (128 * HS_STRIDE)                 // 8704
#define OFF_W0   (OFF_XS + 128 * XS_STRIDE)        // 13312
#define OFF_SCE  (OFF_W0 + FCI * FCH)              // 14336
#define OFF_EAS  (OFF_SCE + MUL * VE * VE)         // 14848
#define OFF_DSS  (OFF_EAS + 128 * 4)               // 15360
#define SMEM_FLOATS (OFF_DSS + 128)                // 15488
#define SMEM_BYTES (SMEM_FLOATS * 4)               // 61952

// Fused edge kernel: FC0+sin -> smem H -> 3xTF32 MMA (W1 pre-split in global)
// -> warp-local TP epilogue -> v4 RED scatter + edge update. 128 edges/block.
__global__ __launch_bounds__(128, 3) void edge_mma_kernel(
    const float* __restrict__ es, const int* __restrict__ src,
    const int* __restrict__ dst, const float* __restrict__ ea_in_p,
    float* __restrict__ ea_out_p, const float* __restrict__ fw0,
    const float* __restrict__ scew)
{
    extern __shared__ float sm[];
    float* Hs   = sm + OFF_HS;    // [128][68] row = edge, col = j (fp32 h)
    float* xs   = sm + OFF_XS;    // [128][36] x[src[e]]
    float* w0s  = sm + OFF_W0;    // FC0 weights
    float* sces = sm + OFF_SCE;   // sce weights
    float* eas  = sm + OFF_EAS;   // [128][4] edge attrs
    int*   dss  = (int*)(sm + OFF_DSS);  // [128] dst

    int tid = threadIdx.x;
    for (int i = tid; i < FCI * FCH; i += 128) w0s[i] = fw0[i];
    for (int i = tid; i < MUL * VE * VE; i += 128) sces[i] = scew[i];
    __syncthreads();

    const float* ea_in = ea_in_p ? ea_in_p : g_ea;
    float* ea_out = ea_out_p ? ea_out_p : g_ea;

    int ge = blockIdx.x * 128 + tid;   // NE = 128*6250, always in range

    // ---- h phase: FC0 + sin for this thread's edge ----
    {
        float scl[FCI];
        const float4* esp = (const float4*)(es + (size_t)ge * FCI);
#pragma unroll
        for (int i = 0; i < 4; i++) {
            float4 tv = esp[i];
            scl[4 * i + 0] = tv.x; scl[4 * i + 1] = tv.y;
            scl[4 * i + 2] = tv.z; scl[4 * i + 3] = tv.w;
        }
        float h[FCH];
#pragma unroll
        for (int j = 0; j < FCH; j++) h[j] = 0.0f;
#pragma unroll
        for (int i = 0; i < FCI; i++) {
            float si = scl[i];
            const float4* wr = (const float4*)&w0s[i * FCH];
#pragma unroll
            for (int j4 = 0; j4 < FCH / 4; j4++) {
                float4 wv = wr[j4];
                h[4 * j4 + 0] += si * wv.x;
                h[4 * j4 + 1] += si * wv.y;
                h[4 * j4 + 2] += si * wv.z;
                h[4 * j4 + 3] += si * wv.w;
            }
        }
        float4* hrow = (float4*)(Hs + tid * HS_STRIDE);
#pragma unroll
        for (int q = 0; q < 16; q++) {
            hrow[q] = make_float4(__sinf(h[4 * q + 0] * 0.25f), __sinf(h[4 * q + 1] * 0.25f),
                                  __sinf(h[4 * q + 2] * 0.25f), __sinf(h[4 * q + 3] * 0.25f));
        }
    }
    int sv = src[ge];
    dss[tid] = dst[ge];
    *(float4*)(eas + tid * 4) = *(const float4*)(ea_in + (size_t)ge * VE);
    {
        const float4* xr = (const float4*)(g_x + (size_t)sv * MUL);
        float4* xd = (float4*)(xs + tid * XS_STRIDE);
#pragma unroll
        for (int q = 0; q < 8; q++) xd[q] = xr[q];
    }
    __syncwarp();   // each warp only consumes rows written by its own threads

    // ---- MMA + epilogue: warp wp owns edges [32*wp, 32*wp+32) ----
    int lane = tid & 31, wp = tid >> 5, g = lane >> 2, t = lane & 3;

    float ear[2][2][4];
    int dlo[2], dhi[2];
#pragma unroll
    for (int mt = 0; mt < 2; mt++) {
        int rl = wp * 32 + mt * 16 + g, rh = rl + 8;
#pragma unroll
        for (int v = 0; v < 4; v++) {
            ear[mt][0][v] = eas[rl * 4 + v];
            ear[mt][1][v] = eas[rh * 4 + v];
        }
        dlo[mt] = dss[rl]; dhi[mt] = dss[rh];
    }

    float racc[2][2][4];
#pragma unroll
    for (int mt = 0; mt < 2; mt++)
#pragma unroll
        for (int i = 0; i < 2; i++)
#pragma unroll
            for (int v = 0; v < 4; v++) racc[mt][i][v] = 0.f;

    int vb = (2 * t) & 3;   // 0 or 2: v-base of this lane's acc pair

#pragma unroll 1
    for (int ng = 0; ng < 4; ng++) {
        float acc[2][4][4];
#pragma unroll
        for (int mt = 0; mt < 2; mt++)
#pragma unroll
            for (int nt = 0; nt < 4; nt++)
#pragma unroll
                for (int i = 0; i < 4; i++) acc[mt][nt][i] = 0.f;

#pragma unroll 1
        for (int k0 = 0; k0 < 64; k0 += 8) {
            uint32_t ahi[2][4], alo[2][4];
#pragma unroll
            for (int mt = 0; mt < 2; mt++) {
                int rb = (wp * 32 + mt * 16 + g) * HS_STRIDE + k0 + t;
                tf32_split(Hs[rb],                     ahi[mt][0], alo[mt][0]);
                tf32_split(Hs[rb + 8 * HS_STRIDE],     ahi[mt][1], alo[mt][1]);
                tf32_split(Hs[rb + 4],                 ahi[mt][2], alo[mt][2]);
                tf32_split(Hs[rb + 8 * HS_STRIDE + 4], ahi[mt][3], alo[mt][3]);
            }
#pragma unroll
            for (int nt = 0; nt < 4; nt++) {
                int nb = (32 * ng + 8 * nt + g) * FCH + k0 + t;
                uint32_t bhi[2], blo[2];
                bhi[0] = __ldg(&g_w1thi[nb]);
                bhi[1] = __ldg(&g_w1thi[nb + 4]);
                blo[0] = __ldg(&g_w1tlo[nb]);
                blo[1] = __ldg(&g_w1tlo[nb + 4]);
#pragma unroll
                for (int mt = 0; mt < 2; mt++) {
                    mma_tf32(acc[mt][nt], ahi[mt], bhi);
                    mma_tf32(acc[mt][nt], ahi[mt], blo);
                    mma_tf32(acc[mt][nt], alo[mt], bhi);
                }
            }
        }

        // ---- epilogue for this n-group (u in [8*ng, 8*ng+8)) ----
#pragma unroll
        for (int mt = 0; mt < 2; mt++) {
            int rl = wp * 32 + mt * 16 + g, rh = rl + 8;
            float efl[4], efh[4];
#pragma unroll
            for (int nt = 0; nt < 4; nt++) {
                float* c = acc[mt][nt];
                float pl = ear[mt][0][vb] * c[0] + ear[mt][0][vb + 1] * c[1];
                float ph = ear[mt][1][vb] * c[2] + ear[mt][1][vb + 1] * c[3];
                pl += __shfl_xor_sync(0xffffffffu, pl, 1);
                ph += __shfl_xor_sync(0xffffffffu, ph, 1);
                int u = 8 * ng + 2 * nt + (t >> 1);
                float el = xs[rl * XS_STRIDE + u] * pl * 0.0625f;
                float eh = xs[rh * XS_STRIDE + u] * ph * 0.0625f;
                efl[nt] = el; efh[nt] = eh;
                // r accumulation (t-pairs duplicate; corrected by 0.5 at the end)
                const float4* sp = (const float4*)&sces[u * 16];
                float4 s0 = sp[0], s1 = sp[1], s2 = sp[2], s3 = sp[3];
                racc[mt][0][0] += el * (ear[mt][0][0] * s0.x + ear[mt][0][1] * s1.x + ear[mt][0][2] * s2.x + ear[mt][0][3] * s3.x);
                racc[mt][0][1] += el * (ear[mt][0][0] * s0.y + ear[mt][0][1] * s1.y + ear[mt][0][2] * s2.y + ear[mt][0][3] * s3.y);
                racc[mt][0][2] += el * (ear[mt][0][0] * s0.z + ear[mt][0][1] * s1.z + ear[mt][0][2] * s2.z + ear[mt][0][3] * s3.z);
                racc[mt][0][3] += el * (ear[mt][0][0] * s0.w + ear[mt][0][1] * s1.w + ear[mt][0][2] * s2.w + ear[mt][0][3] * s3.w);
                racc[mt][1][0] += eh * (ear[mt][1][0] * s0.x + ear[mt][1][1] * s1.x + ear[mt][1][2] * s2.x + ear[mt][1][3] * s3.x);
                racc[mt][1][1] += eh * (ear[mt][1][0] * s0.y + ear[mt][1][1] * s1.y + ear[mt][1][2] * s2.y + ear[mt][1][3] * s3.y);
                racc[mt][1][2] += eh * (ear[mt][1][0] * s0.z + ear[mt][1][1] * s1.z + ear[mt][1][2] * s2.z + ear[mt][1][3] * s3.z);
                racc[mt][1][3] += eh * (ear[mt][1][0] * s0.w + ear[mt][1][1] * s1.w + ear[mt][1][2] * s2.w + ear[mt][1][3] * s3.w);
            }
            // regroup u's for v4 RED: t0 has u{0,2,4,6}+8ng, t2 has u{1,3,5,7}+8ng
            float xl[4], xh[4];
#pragma unroll
            for (int nt = 0; nt < 4; nt++) {
                xl[nt] = __shfl_xor_sync(0xffffffffu, efl[nt], 2);
                xh[nt] = __shfl_xor_sync(0xffffffffu, efh[nt], 2);
            }
            if ((t & 1) == 0) {
                int ubase = 8 * ng + ((t == 0) ? 0 : 4);
                float a0, a1, a2, a3, b0, b1, b2, b3;
                if (t == 0) {
                    a0 = efl[0]; a1 = xl[0]; a2 = efl[1]; a3 = xl[1];
                    b0 = efh[0]; b1 = xh[0]; b2 = efh[1]; b3 = xh[1];
                } else {
                    a0 = xl[2]; a1 = efl[2]; a2 = xl[3]; a3 = efl[3];
                    b0 = xh[2]; b1 = efh[2]; b2 = xh[3]; b3 = efh[3];
                }
                const float sn = 0.25f;  // segment norm 1/sqrt(16)
                red_add_v4(&g_agg[(size_t)dlo[mt] * MUL + ubase], a0 * sn, a1 * sn, a2 * sn, a3 * sn);
                red_add_v4(&g_agg[(size_t)dhi[mt] * MUL + ubase], b0 * sn, b1 * sn, b2 * sn, b3 * sn);
            }
        }
    }

    // ---- finalize edge_out: reduce racc over the 4 lanes of the group ----
#pragma unroll
    for (int mt = 0; mt < 2; mt++)
#pragma unroll
        for (int i = 0; i < 2; i++)
#pragma unroll
            for (int v = 0; v < 4; v++) {
                float val = racc[mt][i][v];
                val += __shfl_xor_sync(0xffffffffu, val, 1);
                val += __shfl_xor_sync(0xffffffffu, val, 2);
                racc[mt][i][v] = val;
            }
    const float C2 = 0.5f * 0.022097086912079608f;  // 0.5 dup-fix * 1/(4*sqrt(128))
    if (t == 0) {
#pragma unroll
        for (int mt = 0; mt < 2; mt++) {
            int rl = wp * 32 + mt * 16 + g, rh = rl + 8;
            size_t el = (size_t)(blockIdx.x * 128 + rl);
            size_t eh = (size_t)(blockIdx.x * 128 + rh);
            float4 ol = make_float4(ear[mt][0][0] + racc[mt][0][0] * C2,
                                    ear[mt][0][1] + racc[mt][0][1] * C2,
                                    ear[mt][0][2] + racc[mt][0][2] * C2,
                                    ear[mt][0][3] + racc[mt][0][3] * C2);
            float4 oh = make_float4(ear[mt][1][0] + racc[mt][1][0] * C2,
                                    ear[mt][1][1] + racc[mt][1][1] * C2,
                                    ear[mt][1][2] + racc[mt][1][2] * C2,
                                    ear[mt][1][3] + racc[mt][1][3] * C2);
            *(float4*)(ea_out + el * VE) = ol;
            *(float4*)(ea_out + eh * VE) = oh;
        }
    }
}

// ---------------------------------------------------------------
extern "C" void kernel_launch(void* const* d_in, const int* in_sizes, int n_in,
                              void* d_out, int out_size)
{
    const float* node_features = (const float*)d_in[0];
    const float* node_attr     = (const float*)d_in[1];
    const int*   edge_src      = (const int*)d_in[2];
    const int*   edge_dst      = (const int*)d_in[3];
    const float* edge_attr     = (const float*)d_in[4];
    const float* edge_scalars  = (const float*)d_in[5];
    const float* sc_w    = (const float*)d_in[6];
    const float* lin1_w  = (const float*)d_in[7];
    const float* lin2_w  = (const float*)d_in[8];
    const float* alpha_w = (const float*)d_in[9];
    const float* sce_w   = (const float*)d_in[10];
    const float* fc_w0   = (const float*)d_in[11];
    const float* fc_w1   = (const float*)d_in[12];
    float* out = (float*)d_out;

    const int need_nf = NN * MUL;
    const int need_both = NN * MUL + NE * VE;
    float* nf_final = (out_size >= need_nf) ? out : nullptr;
    float* ea_final = (out_size >= need_both) ? (out + (size_t)NN * MUL) : nullptr;

    cudaFuncSetAttribute(edge_mma_kernel,
                         cudaFuncAttributeMaxDynamicSharedMemorySize, SMEM_BYTES);

    const int node_grid = (NN + 255) / 256;
    const int edge_grid = NE / 128;   // 6250
    const int zero_grid = (NN * MUL + 255) / 256;
    const int w1_grid = (W_NUMEL * FCH + 255) / 256;

    for (int l = 0; l < 2; l++) {
        const float* nf_in = (l == 0) ? node_features : nullptr;  // null -> g_nf
        const float* ea_in = (l == 0) ? edge_attr : nullptr;      // null -> g_ea
        float* ea_out = (l == 1) ? ea_final : nullptr;            // null -> g_ea
        float* nf_out = (l == 1) ? nf_final : nullptr;            // null -> g_nf

        w1_split_kernel<<<w1_grid, 256>>>(fc_w1 + (size_t)l * FCH * W_NUMEL);
        fctp_dual_kernel<<<2 * node_grid, 256>>>(nf_in, node_attr,
                                                 sc_w + (size_t)l * MUL * AA * MUL,
                                                 lin1_w + (size_t)l * MUL * AA * MUL,
                                                 node_grid);
        zero_agg_kernel<<<zero_grid, 256>>>();
        edge_mma_kernel<<<edge_grid, 128, SMEM_BYTES>>>(
            edge_scalars, edge_src, edge_dst, ea_in, ea_out,
            fc_w0 + (size_t)l * FCI * FCH,
            sce_w + (size_t)l * MUL * VE * VE);
        node_post_kernel<<<node_grid, 256>>>(node_attr,
                                             lin2_w + (size_t)l * MUL * AA * MUL,
                                             alpha_w + (size_t)l * MUL * AA,
                                             nf_out, (l == 0) ? 1 : 0);
    }
}